// round 9
// baseline (speedup 1.0000x reference)
#include <cuda_runtime.h>

#define EPSV 1e-7f
#define NPOS 288     // 2*12*12 output positions
#define KKI  288     // 3*3*32 input votes
#define NC   32
#define PP   16
#define NTH  256
#define NWARP 8
#define IPW  36      // KKI / NWARP

__device__ __forceinline__ float bfly_max(float v) {
    #pragma unroll
    for (int o = 16; o >= 1; o >>= 1) v = fmaxf(v, __shfl_xor_sync(0xffffffffu, v, o));
    return v;
}
__device__ __forceinline__ float bfly_sum(float v) {
    #pragma unroll
    for (int o = 16; o >= 1; o >>= 1) v += __shfl_xor_sync(0xffffffffu, v, o);
    return v;
}

// W re-laid out chunk-major for coalesced warp loads:
// g_W2[i][j][c][q]  (j = output-column chunk r, c = capsule, q fastest)
__device__ float g_W2[KKI * NC * PP];

__global__ void relayout_W_kernel(const float* __restrict__ W) {
    int o = blockIdx.x * 256 + threadIdx.x;
    if (o < KKI * NC * PP) {
        int q = o & 3;
        int c = (o >> 2) & 31;
        int j = (o >> 7) & 3;
        int i = o >> 9;
        g_W2[o] = W[i * 512 + c * 16 + q * 4 + j];
    }
}

__device__ __forceinline__ float dot4(float4 a, float4 b) {
    return fmaf(a.x, b.x, fmaf(a.y, b.y, fmaf(a.z, b.z, a.w * b.w)));
}

// Compute V[i, c, 0..15]; wp is this lane's running W pointer (advances 128 float4/i).
__device__ __forceinline__ void compute_v(const float* __restrict__ sMp, int i,
                                          const float4* __restrict__ wp, float v[16]) {
    const float4* mp = reinterpret_cast<const float4*>(sMp + i * 16);
    float4 m0 = mp[0], m1 = mp[1], m2 = mp[2], m3 = mp[3];
    float4 w0 = wp[0], w1 = wp[32], w2 = wp[64], w3 = wp[96];
    v[0]  = dot4(m0, w0); v[1]  = dot4(m0, w1); v[2]  = dot4(m0, w2); v[3]  = dot4(m0, w3);
    v[4]  = dot4(m1, w0); v[5]  = dot4(m1, w1); v[6]  = dot4(m1, w2); v[7]  = dot4(m1, w3);
    v[8]  = dot4(m2, w0); v[9]  = dot4(m2, w1); v[10] = dot4(m2, w2); v[11] = dot4(m2, w3);
    v[12] = dot4(m3, w0); v[13] = dot4(m3, w1); v[14] = dot4(m3, w2); v[15] = dot4(m3, w3);
}

// Per-iteration statistics. sRedM stride 17; sRedS stride 33.
__device__ __forceinline__ void compute_stats(
    const float* __restrict__ sRedM, const float* __restrict__ sRedS,
    int c, float rscale, float bv, float ba, float inv_temp,
    float M[16], float wgt[16], float& base, float& aj)
{
    float RsRaw = sRedM[c * 17 + 16];
    float Rs = RsRaw * rscale;
    float invR = __fdividef(1.0f, RsRaw);
    float sumlog = 0.0f;
    #pragma unroll
    for (int k = 0; k < 16; k++) {
        float m   = sRedM[c * 17 + k] * invR;
        float s1  = sRedS[c * 33 + k];
        float s2  = sRedS[c * 33 + 16 + k];
        float var = s2 - 2.0f * m * s1 + 288.0f * m * m;
        var = fmaxf(var, 0.0f);
        float sd = sqrtf(var);
        sumlog += __logf(sd + EPSV);
        wgt[k] = __fdividef(0.5f, sd * sd + 1e-30f);
        M[k]   = m;
    }
    float cost = (16.0f * bv + sumlog) * Rs;
    float cmean = bfly_sum(cost) * (1.0f / 32.0f);
    float d = cost - cmean;
    float cstd = sqrtf(bfly_sum(d * d) * (1.0f / 32.0f));
    float acost = ba + __fdividef(cmean - cost, cstd + EPSV);
    aj   = __fdividef(1.0f, 1.0f + __expf(-inv_temp * acost));
    base = __logf(aj + EPSV) - sumlog;
}

__global__ __launch_bounds__(NTH, 3)
void caps_em_kernel(const float* __restrict__ x,
                    const float* __restrict__ beta_v,
                    const float* __restrict__ beta_a,
                    float* __restrict__ out)
{
    __shared__ float sMp[KKI * 16];          // 4608 floats
    __shared__ float sA[KKI];                // 288
    __shared__ float sPart[NWARP * NC * 17]; // 4352
    __shared__ float sRedM[NC * 17];         // 544
    __shared__ float sRedS[NC * 33];         // 1056

    const int tid  = threadIdx.x;
    const int c    = tid & 31;        // capsule
    const int wid  = tid >> 5;
    const int pos  = blockIdx.x;
    const int b  = pos / 144;
    const int rp = pos % 144;
    const int ho = rp / 12, wo = rp % 12;

    // ---- load patch: i = (ki*3+kj)*32 + cin ----
    for (int i = tid; i < KKI; i += NTH) {
        int kk = i >> 5, cin = i & 31;
        int ki = kk / 3, kj = kk % 3;
        const float* src = x + ((((b * 14) + ho + ki) * 14 + (wo + kj)) * 32 + cin) * 17;
        #pragma unroll
        for (int e = 0; e < 16; e++) sMp[i * 16 + e] = src[e];
        sA[i] = src[16];
    }
    __syncthreads();

    const float bv = beta_v[c];
    const float ba = beta_a[c];
    const int i0 = wid * IPW, i1 = i0 + IPW;
    float* myP = sPart + (wid * NC + c) * 17;
    const float4* wbase = reinterpret_cast<const float4*>(g_W2 + i0 * 512) + c;

    // ================= PASS 1: iter 0 (uniform R) + S1/S2 =================
    {
        float Mnum[16], S1[16], S2[16];
        float Rsum = 0.0f;
        #pragma unroll
        for (int k = 0; k < 16; k++) { Mnum[k] = 0.0f; S1[k] = 0.0f; S2[k] = 0.0f; }
        const float4* wp = wbase;
        #pragma unroll 2
        for (int i = i0; i < i1; i++, wp += 128) {
            float v[16];
            compute_v(sMp, i, wp, v);
            float ai = sA[i];
            #pragma unroll
            for (int k = 0; k < 16; k++) {
                S1[k] += v[k];
                S2[k]  = fmaf(v[k], v[k], S2[k]);
                Mnum[k] = fmaf(ai, v[k], Mnum[k]);
            }
            Rsum += ai;
        }
        // --- round A: Mnum + Rsum ---
        #pragma unroll
        for (int k = 0; k < 16; k++) myP[k] = Mnum[k];
        myP[16] = Rsum;
        __syncthreads();
        for (int s = tid; s < NC * 17; s += NTH) {
            float acc = 0.0f;
            #pragma unroll
            for (int w = 0; w < NWARP; w++) acc += sPart[w * (NC * 17) + s];
            sRedM[s] = acc;
        }
        __syncthreads();
        // --- round B: S1 ---
        #pragma unroll
        for (int k = 0; k < 16; k++) myP[k] = S1[k];
        __syncthreads();
        for (int s = tid; s < NC * 17; s += NTH) {
            int cc = s / 17, kk = s - cc * 17;
            if (kk < 16) {
                float acc = 0.0f;
                #pragma unroll
                for (int w = 0; w < NWARP; w++) acc += sPart[w * (NC * 17) + s];
                sRedS[cc * 33 + kk] = acc;
            }
        }
        __syncthreads();
        // --- round C: S2 ---
        #pragma unroll
        for (int k = 0; k < 16; k++) myP[k] = S2[k];
        __syncthreads();
        for (int s = tid; s < NC * 17; s += NTH) {
            int cc = s / 17, kk = s - cc * 17;
            if (kk < 16) {
                float acc = 0.0f;
                #pragma unroll
                for (int w = 0; w < NWARP; w++) acc += sPart[w * (NC * 17) + s];
                sRedS[cc * 33 + 16 + kk] = acc;
            }
        }
        __syncthreads();
    }

    float M[16], wgt[16], base, aj;
    compute_stats(sRedM, sRedS, c, 1.0f / 32.0f, bv, ba, 1.0f, M, wgt, base, aj);

    // Folded Mahalanobis: lp = baseAdj - sum_k (wgt*v + m2)*v
    float m2[16], baseAdj, bmax;
    {
        float cM = 0.0f;
        #pragma unroll
        for (int k = 0; k < 16; k++) { m2[k] = -2.0f * wgt[k] * M[k]; cM = fmaf(wgt[k] * M[k], M[k], cM); }
        baseAdj = base - cM;
        bmax = bfly_max(base);
    }

    // ================= PASS 2 & 3: routing iterations 1, 2 =================
    #pragma unroll 1
    for (int it = 1; it <= 2; it++) {
        float Mnum[16];
        float Rsum = 0.0f;
        #pragma unroll
        for (int k = 0; k < 16; k++) Mnum[k] = 0.0f;

        const float4* wp = wbase;
        #pragma unroll 2
        for (int i = i0; i < i1; i++, wp += 128) {
            float v[16];
            compute_v(sMp, i, wp, v);
            // two-tree Mahalanobis accumulation (shorter serial chain)
            float e0 = 0.0f, e1 = 0.0f;
            #pragma unroll
            for (int k = 0; k < 16; k += 2) {
                float t0 = fmaf(wgt[k], v[k], m2[k]);
                e0 = fmaf(t0, v[k], e0);
                float t1 = fmaf(wgt[k + 1], v[k + 1], m2[k + 1]);
                e1 = fmaf(t1, v[k + 1], e1);
            }
            float lp = baseAdj - (e0 + e1);
            float ex = __expf(lp - bmax);
            float sm = bfly_sum(ex) + 1e-38f;
            float Rw = sA[i] * __fdividef(ex, sm);
            Rsum += Rw;
            #pragma unroll
            for (int k = 0; k < 16; k++) Mnum[k] = fmaf(Rw, v[k], Mnum[k]);
        }
        __syncthreads();
        #pragma unroll
        for (int k = 0; k < 16; k++) myP[k] = Mnum[k];
        myP[16] = Rsum;
        __syncthreads();
        for (int s = tid; s < NC * 17; s += NTH) {
            float acc = 0.0f;
            #pragma unroll
            for (int w = 0; w < NWARP; w++) acc += sPart[w * (NC * 17) + s];
            sRedM[s] = acc;
        }
        __syncthreads();

        compute_stats(sRedM, sRedS, c, 1.0f, bv, ba, 1.0f + (float)it, M, wgt, base, aj);
        if (it < 2) {
            float cM = 0.0f;
            #pragma unroll
            for (int k = 0; k < 16; k++) { m2[k] = -2.0f * wgt[k] * M[k]; cM = fmaf(wgt[k] * M[k], M[k], cM); }
            baseAdj = base - cM;
            bmax = bfly_max(base);
        }
    }

    // ---- write output: [pos][c][0..15] = M, [16] = sigmoid(a_j) ----
    if (wid == 0) {
        float* dst = out + (pos * NC + c) * 17;
        #pragma unroll
        for (int k = 0; k < 16; k++) dst[k] = M[k];
        dst[16] = __fdividef(1.0f, 1.0f + __expf(-aj));
    }
}

extern "C" void kernel_launch(void* const* d_in, const int* in_sizes, int n_in,
                              void* d_out, int out_size) {
    const float* x      = (const float*)d_in[0];
    const float* W      = (const float*)d_in[1];
    const float* beta_v = (const float*)d_in[2];
    const float* beta_a = (const float*)d_in[3];
    float* out = (float*)d_out;

    relayout_W_kernel<<<(KKI * NC * PP + 255) / 256, 256>>>(W);
    caps_em_kernel<<<NPOS, NTH>>>(x, beta_v, beta_a, out);
}

// round 13
// speedup vs baseline: 1.5208x; 1.5208x over previous
#include <cuda_runtime.h>

#define EPSV 1e-7f
#define NPOS 288     // 2*12*12 output positions
#define KKI  288     // 3*3*32 input votes
#define NC   32
#define PP   16
#define NTH  256
#define NWARP 8
#define IPW  36      // KKI / NWARP

__device__ __forceinline__ float bfly_max(float v) {
    #pragma unroll
    for (int o = 16; o >= 1; o >>= 1) v = fmaxf(v, __shfl_xor_sync(0xffffffffu, v, o));
    return v;
}
__device__ __forceinline__ float bfly_sum(float v) {
    #pragma unroll
    for (int o = 16; o >= 1; o >>= 1) v += __shfl_xor_sync(0xffffffffu, v, o);
    return v;
}

// W re-laid out chunk-major for coalesced warp loads:
// g_W2[i][j][c][q]  (j = output-column chunk r, c = capsule, q fastest)
__device__ float g_W2[KKI * NC * PP];

__global__ void relayout_W_kernel(const float* __restrict__ W) {
    int o = blockIdx.x * 256 + threadIdx.x;
    if (o < KKI * NC * PP) {
        int q = o & 3;
        int c = (o >> 2) & 31;
        int j = (o >> 7) & 3;
        int i = o >> 9;
        g_W2[o] = W[i * 512 + c * 16 + q * 4 + j];
    }
}

__device__ __forceinline__ float dot4(float4 a, float4 b) {
    return fmaf(a.x, b.x, fmaf(a.y, b.y, fmaf(a.z, b.z, a.w * b.w)));
}

// Compute V[i, c, 0..15]; wp = this lane's running W pointer (advances 128 float4/i).
__device__ __forceinline__ void compute_v(const float* __restrict__ sMp, int i,
                                          const float4* __restrict__ wp, float v[16]) {
    const float4* mp = reinterpret_cast<const float4*>(sMp + i * 16);
    float4 m0 = mp[0], m1 = mp[1], m2 = mp[2], m3 = mp[3];
    float4 w0 = wp[0], w1 = wp[32], w2 = wp[64], w3 = wp[96];
    v[0]  = dot4(m0, w0); v[1]  = dot4(m0, w1); v[2]  = dot4(m0, w2); v[3]  = dot4(m0, w3);
    v[4]  = dot4(m1, w0); v[5]  = dot4(m1, w1); v[6]  = dot4(m1, w2); v[7]  = dot4(m1, w3);
    v[8]  = dot4(m2, w0); v[9]  = dot4(m2, w1); v[10] = dot4(m2, w2); v[11] = dot4(m2, w3);
    v[12] = dot4(m3, w0); v[13] = dot4(m3, w1); v[14] = dot4(m3, w2); v[15] = dot4(m3, w3);
}

// Per-iteration statistics. sRedM stride 17; sRedS stride 33.
__device__ __forceinline__ void compute_stats(
    const float* __restrict__ sRedM, const float* __restrict__ sRedS,
    int c, float rscale, float bv, float ba, float inv_temp,
    float M[16], float wgt[16], float& base, float& aj)
{
    float RsRaw = sRedM[c * 17 + 16];
    float Rs = RsRaw * rscale;
    float invR = __fdividef(1.0f, RsRaw);
    float sumlog = 0.0f;
    #pragma unroll
    for (int k = 0; k < 16; k++) {
        float m   = sRedM[c * 17 + k] * invR;
        float s1  = sRedS[c * 33 + k];
        float s2  = sRedS[c * 33 + 16 + k];
        float var = s2 - 2.0f * m * s1 + 288.0f * m * m;
        var = fmaxf(var, 0.0f);
        float sd = sqrtf(var);
        sumlog += __logf(sd + EPSV);
        wgt[k] = __fdividef(0.5f, sd * sd + 1e-30f);
        M[k]   = m;
    }
    float cost = (16.0f * bv + sumlog) * Rs;
    float cmean = bfly_sum(cost) * (1.0f / 32.0f);
    float d = cost - cmean;
    float cstd = sqrtf(bfly_sum(d * d) * (1.0f / 32.0f));
    float acost = ba + __fdividef(cmean - cost, cstd + EPSV);
    aj   = __fdividef(1.0f, 1.0f + __expf(-inv_temp * acost));
    base = __logf(aj + EPSV) - sumlog;
}

__global__ __launch_bounds__(NTH, 2)
void caps_em_kernel(const float* __restrict__ x,
                    const float* __restrict__ beta_v,
                    const float* __restrict__ beta_a,
                    float* __restrict__ out)
{
    __shared__ float sMp[KKI * 16];          // 4608 floats
    __shared__ float sA[KKI];                // 288
    __shared__ float sPart[NWARP * NC * 17]; // 4352
    __shared__ float sRedM[NC * 17];         // 544
    __shared__ float sRedS[NC * 33];         // 1056

    const int tid  = threadIdx.x;
    const int c    = tid & 31;        // capsule
    const int wid  = tid >> 5;
    const int pos  = blockIdx.x;
    const int b  = pos / 144;
    const int rp = pos % 144;
    const int ho = rp / 12, wo = rp % 12;

    // ---- coalesced patch load ----
    // x row for tap (ki,kj): 544 contiguous floats; i = kk*32 + cin.
    for (int idx = tid; idx < KKI * 17; idx += NTH) {
        int kk  = idx / 544;
        int off = idx - kk * 544;
        int ki = kk / 3, kj = kk - ki * 3;
        float val = x[(size_t)(((b * 14) + ho + ki) * 14 + (wo + kj)) * 544 + off];
        int cin = off / 17;
        int e   = off - cin * 17;
        int i   = kk * 32 + cin;
        if (e < 16) sMp[i * 16 + e] = val;
        else        sA[i] = val;
    }
    __syncthreads();

    const float bv = beta_v[c];
    const float ba = beta_a[c];
    const int i0 = wid * IPW, i1 = i0 + IPW;
    float* myP = sPart + (wid * NC + c) * 17;
    const float4* wbase = reinterpret_cast<const float4*>(g_W2 + i0 * 512) + c;

    // ================= PASS 1: iter 0 (uniform R) + S1/S2 =================
    {
        float Mnum[16], S1[16], S2[16];
        float Rsum = 0.0f;
        #pragma unroll
        for (int k = 0; k < 16; k++) { Mnum[k] = 0.0f; S1[k] = 0.0f; S2[k] = 0.0f; }
        const float4* wp = wbase;
        #pragma unroll 2
        for (int i = i0; i < i1; i++, wp += 128) {
            float v[16];
            compute_v(sMp, i, wp, v);
            float ai = sA[i];
            #pragma unroll
            for (int k = 0; k < 16; k++) {
                S1[k] += v[k];
                S2[k]  = fmaf(v[k], v[k], S2[k]);
                Mnum[k] = fmaf(ai, v[k], Mnum[k]);
            }
            Rsum += ai;
        }
        // --- round A: Mnum + Rsum ---
        #pragma unroll
        for (int k = 0; k < 16; k++) myP[k] = Mnum[k];
        myP[16] = Rsum;
        __syncthreads();
        for (int s = tid; s < NC * 17; s += NTH) {
            float acc = 0.0f;
            #pragma unroll
            for (int w = 0; w < NWARP; w++) acc += sPart[w * (NC * 17) + s];
            sRedM[s] = acc;
        }
        __syncthreads();
        // --- round B: S1 ---
        #pragma unroll
        for (int k = 0; k < 16; k++) myP[k] = S1[k];
        __syncthreads();
        for (int s = tid; s < NC * 17; s += NTH) {
            int cc = s / 17, kk = s - cc * 17;
            if (kk < 16) {
                float acc = 0.0f;
                #pragma unroll
                for (int w = 0; w < NWARP; w++) acc += sPart[w * (NC * 17) + s];
                sRedS[cc * 33 + kk] = acc;
            }
        }
        __syncthreads();
        // --- round C: S2 ---
        #pragma unroll
        for (int k = 0; k < 16; k++) myP[k] = S2[k];
        __syncthreads();
        for (int s = tid; s < NC * 17; s += NTH) {
            int cc = s / 17, kk = s - cc * 17;
            if (kk < 16) {
                float acc = 0.0f;
                #pragma unroll
                for (int w = 0; w < NWARP; w++) acc += sPart[w * (NC * 17) + s];
                sRedS[cc * 33 + 16 + kk] = acc;
            }
        }
        __syncthreads();
    }

    float M[16], wgt[16], base, aj;
    compute_stats(sRedM, sRedS, c, 1.0f / 32.0f, bv, ba, 1.0f, M, wgt, base, aj);

    // Folded Mahalanobis: lp = baseAdj - sum_k (wgt*v + m2)*v
    float m2[16], baseAdj, bmax;
    {
        float cM = 0.0f;
        #pragma unroll
        for (int k = 0; k < 16; k++) { m2[k] = -2.0f * wgt[k] * M[k]; cM = fmaf(wgt[k] * M[k], M[k], cM); }
        baseAdj = base - cM;
        bmax = bfly_max(base);
    }

    // ================= PASS 2 & 3: routing iterations 1, 2 =================
    #pragma unroll 1
    for (int it = 1; it <= 2; it++) {
        float Mnum[16];
        float Rsum = 0.0f;
        #pragma unroll
        for (int k = 0; k < 16; k++) Mnum[k] = 0.0f;

        const float4* wp = wbase;
        #pragma unroll 2
        for (int i = i0; i < i1; i++, wp += 128) {
            float v[16];
            compute_v(sMp, i, wp, v);
            // two-tree Mahalanobis accumulation (shorter serial chain)
            float e0 = 0.0f, e1 = 0.0f;
            #pragma unroll
            for (int k = 0; k < 16; k += 2) {
                float t0 = fmaf(wgt[k], v[k], m2[k]);
                e0 = fmaf(t0, v[k], e0);
                float t1 = fmaf(wgt[k + 1], v[k + 1], m2[k + 1]);
                e1 = fmaf(t1, v[k + 1], e1);
            }
            float lp = baseAdj - (e0 + e1);
            float ex = __expf(lp - bmax);
            float sm = bfly_sum(ex) + 1e-38f;
            float Rw = sA[i] * __fdividef(ex, sm);
            Rsum += Rw;
            #pragma unroll
            for (int k = 0; k < 16; k++) Mnum[k] = fmaf(Rw, v[k], Mnum[k]);
        }
        __syncthreads();
        #pragma unroll
        for (int k = 0; k < 16; k++) myP[k] = Mnum[k];
        myP[16] = Rsum;
        __syncthreads();
        for (int s = tid; s < NC * 17; s += NTH) {
            float acc = 0.0f;
            #pragma unroll
            for (int w = 0; w < NWARP; w++) acc += sPart[w * (NC * 17) + s];
            sRedM[s] = acc;
        }
        __syncthreads();

        compute_stats(sRedM, sRedS, c, 1.0f, bv, ba, 1.0f + (float)it, M, wgt, base, aj);
        if (it < 2) {
            float cM = 0.0f;
            #pragma unroll
            for (int k = 0; k < 16; k++) { m2[k] = -2.0f * wgt[k] * M[k]; cM = fmaf(wgt[k] * M[k], M[k], cM); }
            baseAdj = base - cM;
            bmax = bfly_max(base);
        }
    }

    // ---- coalesced output: stage through sRedS (dead after final stats) ----
    __syncthreads();  // all warps done reading sRedS in compute_stats before overwrite
    if (wid == 0) {
        #pragma unroll
        for (int k = 0; k < 16; k++) sRedS[c * 17 + k] = M[k];
        sRedS[c * 17 + 16] = __fdividef(1.0f, 1.0f + __expf(-aj));
    }
    __syncthreads();
    float* dst = out + (size_t)pos * (NC * 17);
    for (int t = tid; t < NC * 17; t += NTH) dst[t] = sRedS[t];
}

extern "C" void kernel_launch(void* const* d_in, const int* in_sizes, int n_in,
                              void* d_out, int out_size) {
    const float* x      = (const float*)d_in[0];
    const float* W      = (const float*)d_in[1];
    const float* beta_v = (const float*)d_in[2];
    const float* beta_a = (const float*)d_in[3];
    float* out = (float*)d_out;

    relayout_W_kernel<<<(KKI * NC * PP + 255) / 256, 256>>>(W);
    caps_em_kernel<<<NPOS, NTH>>>(x, beta_v, beta_a, out);
}